// round 10
// baseline (speedup 1.0000x reference)
#include <cuda_runtime.h>

// FMREDynamicDropout: out = x * bernoulli_mask(threefry2x32, keep_prob[c])
// x: [32, 384, 56, 56] fp32, feature_importance: [384] fp32
//
// JAX (threefry_partitionable) semantics, verified bit-exact since R2:
//   key(42) -> (0, 42); ks2 = 0 ^ 42 ^ 0x1BD11BDA = 0x1BD11BF0
//   per element i: hash counter words (0, i); bits[i] = o0 ^ o1
//   mask = bits < (ceil(keep[c] * 2^23) << 9)   (pure uint compare)
//
// R9: alu-pipe floor attack. Evidence (R2..R8): kernel is pinned at ~95-97us
// by the GUARANTEED-alu ops (20 SHF + 21 LOP3 + epi ~= 45/elem @ 0.5/cyc);
// ptxas auto-balances plain adds (IMAD<->IADD3) so add-steering is ~neutral.
// Fix: move 6 rotations (3x rot15, 3x rot26) off the alu pipe using
//   rotl(x,r) = (x*M) | __umulhi(x,M),  M = 2^r passed as a RUNTIME ARG:
// two scalar IMADs (fma pipe, no 64-bit reg pairs, no asm barriers -- the
// failure modes of R3/R4/R7) + one fused LOP3 (lo|hi)^x0 on alu.
// Per-elem target: alu ~39, fma ~42 (ptxas balances remaining adds).

#define NCH   384
#define HW    3136u
#define NTOT  38535168u   // 32*384*56*56
#define KS2   0x1BD11BF0u

__device__ unsigned g_thresh[NCH];   // pre-shifted: ceil(keep*2^23) << 9

// ---------------- prep: min/max over feature_importance, integer thresholds ----
__global__ void prep_kernel(const float* __restrict__ fi) {
    int t = threadIdx.x;            // 384 threads
    float v = fi[t];
    float mn = v, mx = v;
    #pragma unroll
    for (int o = 16; o > 0; o >>= 1) {
        mn = fminf(mn, __shfl_xor_sync(0xffffffffu, mn, o));
        mx = fmaxf(mx, __shfl_xor_sync(0xffffffffu, mx, o));
    }
    __shared__ float smn[12], smx[12];
    if ((t & 31) == 0) { smn[t >> 5] = mn; smx[t >> 5] = mx; }
    __syncthreads();
    if (t == 0) {
        float a = smn[0], b = smx[0];
        #pragma unroll
        for (int i = 1; i < 12; i++) { a = fminf(a, smn[i]); b = fmaxf(b, smx[i]); }
        smn[0] = a; smx[0] = b;
    }
    __syncthreads();
    float fmin = smn[0], fmax = smx[0];
    // match reference fp32 op ordering (no fma contraction)
    float scaled = __fdiv_rn(__fsub_rn(v, fmin), __fsub_rn(fmax, fmin));
    float rate   = __fadd_rn(0.1f, __fmul_rn(0.4f, __fsub_rn(1.0f, scaled)));
    float keep   = __fsub_rn(1.0f, rate);
    unsigned Tm = (unsigned)ceilf(__fmul_rn(keep, 8388608.0f));   // <= 0.9*2^23
    g_thresh[t] = Tm << 9;
}

// SHF round: add (ptxas-balanced) + funnel-shift (alu) + xor (alu)
#define TFR(rot) do { x0 = x1 * ONE + x0;                               \
                      x1 = __funnelshift_l(x1, x1, (rot)) ^ x0; } while (0)
// MUL round: rotate via two scalar IMADs (fma pipe; M is a runtime value,
// cannot be strength-reduced) + single fused LOP3 (lo|hi)^x0 (alu)
#define TFW(M)   do { x0 = x1 * ONE + x0;                               \
                      x1 = ((x1 * (M)) | __umulhi(x1, (M))) ^ x0; } while (0)

// returns o0 ^ o1 for counter words (0, i), key (0, 42)
__device__ __forceinline__ unsigned tf_bits(unsigned i, unsigned ONE,
                                            unsigned M15, unsigned M26) {
    unsigned x1 = i * ONE + 42u;            // counter + ks1
    unsigned x0 = x1;                       // round-1 add: 0 + x1  (copy)
    x1 = __funnelshift_l(x1, x1, 13) ^ x0;  // round 1  (rot 13)
    TFW(M15); TFW(M26); TFR(6);             // rounds 2-4
    x0 = x0 * ONE + 42u;                    // inject: x0 += ks1
    x1 = x1 * ONE + (KS2 + 1u);             //         x1 += ks2 + 1
    TFR(17); TFR(29); TFR(16); TFR(24);     // rounds 5-8
    x0 = x0 * ONE + KS2;                    // inject: x0 += ks2
    x1 = x1 * ONE + 2u;                     //         x1 += ks0 + 2
    TFR(13); TFW(M15); TFW(M26); TFR(6);    // rounds 9-12
    x1 = x1 * ONE + 45u;                    // inject: x1 += ks1+3 (x0 += 0)
    TFR(17); TFR(29); TFR(16); TFR(24);     // rounds 13-16
    x0 = x0 * ONE + 42u;                    // inject: x0 += ks1
    x1 = x1 * ONE + (KS2 + 4u);             //         x1 += ks2 + 4
    TFR(13); TFW(M15); TFW(M26); TFR(6);    // rounds 17-20
    x0 = x0 * ONE + KS2;                    // final inject x0 += ks2
    x1 = x1 * ONE + 5u;                     //              x1 += ks0 + 5
    return x0 ^ x1;                         // output xor
}

// ---------------- main: 8 consecutive elements (two float4) per thread -------
__global__ void __launch_bounds__(256) drop_kernel(const float* __restrict__ x,
                                                   float* __restrict__ out,
                                                   unsigned ONE,
                                                   unsigned M15, unsigned M26) {
    unsigned j = (blockIdx.x * 256u + threadIdx.x) * 8u;   // j < NTOT, 8 | HW
    unsigned T = g_thresh[(j / HW) % (unsigned)NCH];       // one channel per thread

    float4 a = *reinterpret_cast<const float4*>(x + j);
    float4 b = *reinterpret_cast<const float4*>(x + j + 4);

    unsigned m[8];
    #pragma unroll
    for (int k = 0; k < 8; k++)
        m[k] = tf_bits(j + (unsigned)k, ONE, M15, M26);

    float4 oa, ob;
    oa.x = (m[0] < T) ? a.x : 0.0f;
    oa.y = (m[1] < T) ? a.y : 0.0f;
    oa.z = (m[2] < T) ? a.z : 0.0f;
    oa.w = (m[3] < T) ? a.w : 0.0f;
    ob.x = (m[4] < T) ? b.x : 0.0f;
    ob.y = (m[5] < T) ? b.y : 0.0f;
    ob.z = (m[6] < T) ? b.z : 0.0f;
    ob.w = (m[7] < T) ? b.w : 0.0f;

    *reinterpret_cast<float4*>(out + j)     = oa;
    *reinterpret_cast<float4*>(out + j + 4) = ob;
}

extern "C" void kernel_launch(void* const* d_in, const int* in_sizes, int n_in,
                              void* d_out, int out_size) {
    const float* x  = (const float*)d_in[0];
    const float* fi = (const float*)d_in[1];
    if (n_in >= 2 && in_sizes[0] == NCH) {   // robust to input ordering
        x  = (const float*)d_in[1];
        fi = (const float*)d_in[0];
    }
    prep_kernel<<<1, NCH>>>(fi);
    // runtime args: ONE=1 (add steering hint), M15=2^15, M26=2^26 (rotation
    // multipliers -- runtime values cannot be strength-reduced to shifts).
    // NTOT / 8 elems-per-thread / 256 threads = 18816 blocks, no remainder
    drop_kernel<<<18816, 256>>>(x, (float*)d_out, 1u, 1u << 15, 1u << 26);
}